// round 9
// baseline (speedup 1.0000x reference)
#include <cuda_runtime.h>
#include <cstdint>
#include <cstddef>

// ---------------------------------------------------------------------------
// Problem dims (fixed)
// ---------------------------------------------------------------------------
#define BATCH 64
#define SEQ   2048
#define IND   256
#define UNITS 256
#define M_TOTAL (BATCH * SEQ)          // 131072

typedef unsigned long long ull;

// ---------------------------------------------------------------------------
// Device-global scratch (no runtime allocation allowed)
// ---------------------------------------------------------------------------
__device__ float g_xf[(size_t)M_TOTAL * UNITS];    // 128 MB
__device__ float g_xs[(size_t)M_TOTAL * UNITS];    // 128 MB
// L2-streamed weight tier, pre-packed as ulonglong2 (2 k-pairs each):
// index ((m*2 + kh)*8 + j)*256 + u   covers k = kh*128 + 96 + 4j .. +3
__device__ ulonglong2 g_wtier[2 * 2 * 8 * 256];    // 128 KB

// ---------------------------------------------------------------------------
// Packed f32x2 helpers
// ---------------------------------------------------------------------------
__device__ __forceinline__ void fma2(ull& d, ull a, ull b) {
    asm("fma.rn.f32x2 %0, %1, %2, %0;" : "+l"(d) : "l"(a), "l"(b));
}
__device__ __forceinline__ void add2(ull& d, ull a) {
    asm("add.rn.f32x2 %0, %0, %1;" : "+l"(d) : "l"(a));
}
__device__ __forceinline__ ull pack2(float x, float y) {
    ull r;
    asm("mov.b64 %0, {%1, %2};" : "=l"(r)
        : "r"(__float_as_uint(x)), "r"(__float_as_uint(y)));
    return r;
}
__device__ __forceinline__ float2 unpack2(ull v) {
    unsigned lo, hi;
    asm("mov.b64 {%0, %1}, %2;" : "=r"(lo), "=r"(hi) : "l"(v));
    return make_float2(__uint_as_float(lo), __uint_as_float(hi));
}
__device__ __forceinline__ ulonglong2 ldcg128(const ulonglong2* p) {
    ulonglong2 v;
    asm volatile("ld.global.cg.v2.u64 {%0, %1}, [%2];"
                 : "=l"(v.x), "=l"(v.y) : "l"(p));
    return v;
}

// ---------------------------------------------------------------------------
// Prep: pack the L2-streamed weight tier
// ---------------------------------------------------------------------------
__global__ void prep_wtier(const float* __restrict__ Uf,
                           const float* __restrict__ Us) {
    int idx = blockIdx.x * blockDim.x + threadIdx.x;   // 0..8191
    int u  = idx & 255;
    int j  = (idx >> 8) & 7;
    int kh = (idx >> 11) & 1;
    int m  = idx >> 12;
    const float* U = m ? Us : Uf;
    int k = kh * 128 + 96 + 4 * j;
    ulonglong2 e;
    e.x = pack2(U[(size_t)k       * UNITS + u], U[(size_t)(k + 1) * UNITS + u]);
    e.y = pack2(U[(size_t)(k + 2) * UNITS + u], U[(size_t)(k + 3) * UNITS + u]);
    g_wtier[idx] = e;
}

// ---------------------------------------------------------------------------
// Phase 1: xf = X @ W_f + b_f ; xs = X @ W_s + b_s   (unchanged)
// ---------------------------------------------------------------------------
#define BM 128
#define BN 128
#define BK 16

__global__ __launch_bounds__(256, 2)
void gemm_in(const float* __restrict__ X,
             const float* __restrict__ Wf, const float* __restrict__ bf,
             const float* __restrict__ Ws, const float* __restrict__ bs) {
    __shared__ ull   sA[BK][BM + 2];
    __shared__ float sB[BK][BN];

    const int tid = threadIdx.x;
    const int which = blockIdx.y;
    const float* W    = (which < 2) ? Wf : Ws;
    const float* bias = (which < 2) ? bf : bs;
    float*       out  = (which < 2) ? g_xf : g_xs;
    const int    n0   = (which & 1) * BN;
    const size_t m0   = (size_t)blockIdx.x * BM;

    const int tx = tid & 15;
    const int ty = tid >> 4;

    ull acc[8][4];
#pragma unroll
    for (int i = 0; i < 8; i++)
#pragma unroll
        for (int j = 0; j < 4; j++) acc[i][j] = 0ull;

    for (int k0 = 0; k0 < IND; k0 += BK) {
#pragma unroll
        for (int it = 0; it < 2; it++) {
            int s   = tid + it * 256;
            int row = s >> 2;
            int kq  = (s & 3) * 4;
            float4 v = *(const float4*)&X[(m0 + row) * IND + k0 + kq];
            sA[kq + 0][row] = pack2(v.x, v.x);
            sA[kq + 1][row] = pack2(v.y, v.y);
            sA[kq + 2][row] = pack2(v.z, v.z);
            sA[kq + 3][row] = pack2(v.w, v.w);
        }
#pragma unroll
        for (int it = 0; it < 2; it++) {
            int s  = tid + it * 256;
            int kr = s >> 5;
            int nq = (s & 31) * 4;
            *(float4*)&sB[kr][nq] =
                *(const float4*)&W[(size_t)(k0 + kr) * UNITS + n0 + nq];
        }
        __syncthreads();

#pragma unroll
        for (int k = 0; k < BK; k++) {
            ull a[8];
#pragma unroll
            for (int i = 0; i < 8; i++) a[i] = sA[k][ty * 8 + i];
            const ull* b2 = (const ull*)&sB[k][tx * 8];
            ull b[4];
#pragma unroll
            for (int j = 0; j < 4; j++) b[j] = b2[j];
#pragma unroll
            for (int i = 0; i < 8; i++)
#pragma unroll
                for (int j = 0; j < 4; j++) fma2(acc[i][j], a[i], b[j]);
        }
        __syncthreads();
    }

    float bv[8];
#pragma unroll
    for (int j = 0; j < 8; j++) bv[j] = bias[n0 + tx * 8 + j];
#pragma unroll
    for (int i = 0; i < 8; i++) {
        size_t row = m0 + ty * 8 + i;
        float2 r0 = unpack2(acc[i][0]);
        float2 r1 = unpack2(acc[i][1]);
        float2 r2 = unpack2(acc[i][2]);
        float2 r3 = unpack2(acc[i][3]);
        float4 o0 = make_float4(r0.x + bv[0], r0.y + bv[1],
                                r1.x + bv[2], r1.y + bv[3]);
        float4 o1 = make_float4(r2.x + bv[4], r2.y + bv[5],
                                r3.x + bv[6], r3.y + bv[7]);
        *(float4*)&out[row * UNITS + n0 + tx * 8]     = o0;
        *(float4*)&out[row * UNITS + n0 + tx * 8 + 4] = o1;
    }
}

// ---------------------------------------------------------------------------
// Phase 2: scan. 64 CTAs (one per batch), 512 threads, NO clusters.
// Thread = (unit u = t>>1, k-half kh = t&1); the two halves of a unit are
// adjacent lanes -> partial combine is shfl.bfly(1). 2 __syncthreads per step.
// Weight tiers per thread per matrix (64 pairs over its 128-wide k-half):
//   vh-slot j (each slot = ulonglong2 = 4 floats of h = 2 pairs):
//   j 0..9   -> RF      (20 pairs, 40 regs/matrix)
//   j 10..23 -> smem    (28 pairs, 229KB total)
//   j 24..31 -> L2 tier (16 pairs, streamed each step, prefetched early)
// ---------------------------------------------------------------------------
#define RF_J 10
#define SM_J 14
#define L2_J 8
#define SMEM_SCAN (2 * SM_J * 512 * 16 + 2 * 256 * 4)   // 229376 + 2048 = 231424

__device__ __forceinline__ float matvec_half(const ulonglong2* __restrict__ vh,
                                             const ull (&rW)[2 * RF_J],
                                             const ulonglong2* __restrict__ sW,
                                             const ulonglong2* __restrict__ gW,
                                             int t) {
    // early-issue first L2 batch (independent of h)
    ulonglong2 gl0 = ldcg128(gW + 0 * 256);
    ulonglong2 gl1 = ldcg128(gW + 1 * 256);
    ulonglong2 gl2 = ldcg128(gW + 2 * 256);
    ulonglong2 gl3 = ldcg128(gW + 3 * 256);

    ull a0 = 0, a1 = 0, a2 = 0, a3 = 0;
#pragma unroll
    for (int j = 0; j < RF_J; j++) {
        ulonglong2 hv = vh[j];
        fma2(a0, hv.x, rW[2 * j]);
        fma2(a1, hv.y, rW[2 * j + 1]);
    }
    // consume batch 1 (L2 latency hidden under the RF loop)
    {
        ulonglong2 hv;
        hv = vh[RF_J + SM_J + 0]; fma2(a0, hv.x, gl0.x); fma2(a1, hv.y, gl0.y);
        hv = vh[RF_J + SM_J + 1]; fma2(a0, hv.x, gl1.x); fma2(a1, hv.y, gl1.y);
        hv = vh[RF_J + SM_J + 2]; fma2(a0, hv.x, gl2.x); fma2(a1, hv.y, gl2.y);
        hv = vh[RF_J + SM_J + 3]; fma2(a0, hv.x, gl3.x); fma2(a1, hv.y, gl3.y);
    }
    // issue second L2 batch
    gl0 = ldcg128(gW + 4 * 256);
    gl1 = ldcg128(gW + 5 * 256);
    gl2 = ldcg128(gW + 6 * 256);
    gl3 = ldcg128(gW + 7 * 256);
#pragma unroll
    for (int j = 0; j < SM_J; j++) {
        ulonglong2 hv = vh[RF_J + j];
        ulonglong2 wv = sW[j * 512 + t];
        fma2(a2, hv.x, wv.x);
        fma2(a3, hv.y, wv.y);
    }
    {
        ulonglong2 hv;
        hv = vh[RF_J + SM_J + 4]; fma2(a0, hv.x, gl0.x); fma2(a1, hv.y, gl0.y);
        hv = vh[RF_J + SM_J + 5]; fma2(a0, hv.x, gl1.x); fma2(a1, hv.y, gl1.y);
        hv = vh[RF_J + SM_J + 6]; fma2(a0, hv.x, gl2.x); fma2(a1, hv.y, gl2.y);
        hv = vh[RF_J + SM_J + 7]; fma2(a0, hv.x, gl3.x); fma2(a1, hv.y, gl3.y);
    }
    add2(a0, a1);
    add2(a2, a3);
    add2(a0, a2);
    float2 r = unpack2(a0);
    return r.x + r.y;
}

__global__ __launch_bounds__(512, 1)
void mgu_scan(const float* __restrict__ Uf, const float* __restrict__ Us,
              float* __restrict__ out) {
    extern __shared__ char smem[];
    ulonglong2* sWf = (ulonglong2*)smem;                 // [SM_J][512]
    ulonglong2* sWs = sWf + SM_J * 512;
    float* sh  = (float*)(sWs + SM_J * 512);             // 256 floats
    float* sfh = sh + 256;

    const int t  = threadIdx.x;
    const int u  = t >> 1;
    const int kh = t & 1;
    const int b  = blockIdx.x;
    const int k0 = kh * 128;

    // ---- RF tier preload: pairs p = 0..19 -> k = k0 + 2p ----
    ull rF[2 * RF_J], rS[2 * RF_J];
#pragma unroll
    for (int p = 0; p < 2 * RF_J; p++) {
        rF[p] = pack2(Uf[(size_t)(k0 + 2 * p)     * UNITS + u],
                      Uf[(size_t)(k0 + 2 * p + 1) * UNITS + u]);
        rS[p] = pack2(Us[(size_t)(k0 + 2 * p)     * UNITS + u],
                      Us[(size_t)(k0 + 2 * p + 1) * UNITS + u]);
    }
    // ---- smem tier preload: slot j -> k = k0 + 40 + 4j ----
#pragma unroll
    for (int j = 0; j < SM_J; j++) {
        int k = k0 + 40 + 4 * j;
        sWf[j * 512 + t] = make_ulonglong2(
            pack2(Uf[(size_t)k       * UNITS + u], Uf[(size_t)(k + 1) * UNITS + u]),
            pack2(Uf[(size_t)(k + 2) * UNITS + u], Uf[(size_t)(k + 3) * UNITS + u]));
        sWs[j * 512 + t] = make_ulonglong2(
            pack2(Us[(size_t)k       * UNITS + u], Us[(size_t)(k + 1) * UNITS + u]),
            pack2(Us[(size_t)(k + 2) * UNITS + u], Us[(size_t)(k + 3) * UNITS + u]));
    }
    if (kh == 0) sh[u] = 0.0f;      // h0 = 0
    float h_reg = 0.0f;
    __syncthreads();

    const ulonglong2* vh_h  = (const ulonglong2*)sh  + kh * 32;
    const ulonglong2* vh_fh = (const ulonglong2*)sfh + kh * 32;
    const ulonglong2* gWf = g_wtier + (size_t)((0 * 2 + kh) * 8) * 256 + u;
    const ulonglong2* gWs = g_wtier + (size_t)((1 * 2 + kh) * 8) * 256 + u;

    size_t xoff = ((size_t)b * SEQ) * UNITS + u;

    for (int step = 0; step < SEQ; step++) {
        float xf_v = __ldcg(&g_xf[xoff]);
        float xs_v = __ldcg(&g_xs[xoff]);

        // ---- matvec 1: h @ U_f ----
        float p1 = matvec_half(vh_h, rF, sWf, gWf, t);
        p1 += __shfl_xor_sync(0xffffffffu, p1, 1);
        float fpre = xf_v + p1;
        float f = 1.0f / (1.0f + __expf(-fpre));
        float fh = f * h_reg;
        if (kh == 0) sfh[u] = fh;
        __syncthreads();

        // ---- matvec 2: (f*h) @ U_s ----
        float p2 = matvec_half(vh_fh, rS, sWs, gWs, t);
        p2 += __shfl_xor_sync(0xffffffffu, p2, 1);
        float spre = xs_v + p2;
        float ax = fabsf(spre);
        float e  = __expf(-2.0f * ax);
        float th = (1.0f - e) / (1.0f + e);          // overflow-safe tanh
        th = copysignf(th, spre);

        float hn = h_reg + f * (th - h_reg);         // (1-f)h + f*th
        if (kh == 0) { out[xoff] = hn; sh[u] = hn; }
        h_reg = hn;
        xoff += UNITS;
        __syncthreads();
    }
}

// ---------------------------------------------------------------------------
// Entry point
// ---------------------------------------------------------------------------
extern "C" void kernel_launch(void* const* d_in, const int* in_sizes, int n_in,
                              void* d_out, int out_size) {
    const float* X  = (const float*)d_in[0];
    const float* Wf = (const float*)d_in[1];
    const float* Uf = (const float*)d_in[2];
    const float* bf = (const float*)d_in[3];
    const float* Ws = (const float*)d_in[4];
    const float* Us = (const float*)d_in[5];
    const float* bs = (const float*)d_in[6];
    float* out = (float*)d_out;
    (void)in_sizes; (void)n_in; (void)out_size;

    cudaFuncSetAttribute(mgu_scan,
                         cudaFuncAttributeMaxDynamicSharedMemorySize, SMEM_SCAN);

    prep_wtier<<<32, 256>>>(Uf, Us);
    gemm_in<<<dim3(M_TOTAL / BM, 4), 256>>>(X, Wf, bf, Ws, bs);
    mgu_scan<<<BATCH, 512, SMEM_SCAN>>>(Uf, Us, out);
}

// round 11
// speedup vs baseline: 2.0424x; 2.0424x over previous
#include <cuda_runtime.h>
#include <cstdint>
#include <cstddef>

// ---------------------------------------------------------------------------
// Problem dims (fixed)
// ---------------------------------------------------------------------------
#define BATCH 64
#define SEQ   2048
#define IND   256
#define UNITS 256
#define M_TOTAL (BATCH * SEQ)          // 131072

typedef unsigned long long ull;

// ---------------------------------------------------------------------------
// Device-global scratch (no runtime allocation allowed)
// ---------------------------------------------------------------------------
__device__ float g_xf[(size_t)M_TOTAL * UNITS];    // 128 MB
__device__ float g_xs[(size_t)M_TOTAL * UNITS];    // 128 MB

// ---------------------------------------------------------------------------
// Packed f32x2 helpers
// ---------------------------------------------------------------------------
__device__ __forceinline__ void fma2(ull& d, ull a, ull b) {
    asm("fma.rn.f32x2 %0, %1, %2, %0;" : "+l"(d) : "l"(a), "l"(b));
}
__device__ __forceinline__ void add2(ull& d, ull a) {
    asm("add.rn.f32x2 %0, %0, %1;" : "+l"(d) : "l"(a));
}
__device__ __forceinline__ ull pack2(float x, float y) {
    ull r;
    asm("mov.b64 %0, {%1, %2};" : "=l"(r)
        : "r"(__float_as_uint(x)), "r"(__float_as_uint(y)));
    return r;
}
__device__ __forceinline__ float2 unpack2(ull v) {
    unsigned lo, hi;
    asm("mov.b64 {%0, %1}, %2;" : "=r"(lo), "=r"(hi) : "l"(v));
    return make_float2(__uint_as_float(lo), __uint_as_float(hi));
}

// ---------------------------------------------------------------------------
// Phase 1: xf = X @ W_f + b_f ; xs = X @ W_s + b_s   (unchanged from R6)
// ---------------------------------------------------------------------------
#define BM 128
#define BN 128
#define BK 16

__global__ __launch_bounds__(256, 2)
void gemm_in(const float* __restrict__ X,
             const float* __restrict__ Wf, const float* __restrict__ bf,
             const float* __restrict__ Ws, const float* __restrict__ bs) {
    __shared__ ull   sA[BK][BM + 2];
    __shared__ float sB[BK][BN];

    const int tid = threadIdx.x;
    const int which = blockIdx.y;
    const float* W    = (which < 2) ? Wf : Ws;
    const float* bias = (which < 2) ? bf : bs;
    float*       out  = (which < 2) ? g_xf : g_xs;
    const int    n0   = (which & 1) * BN;
    const size_t m0   = (size_t)blockIdx.x * BM;

    const int tx = tid & 15;
    const int ty = tid >> 4;

    ull acc[8][4];
#pragma unroll
    for (int i = 0; i < 8; i++)
#pragma unroll
        for (int j = 0; j < 4; j++) acc[i][j] = 0ull;

    for (int k0 = 0; k0 < IND; k0 += BK) {
#pragma unroll
        for (int it = 0; it < 2; it++) {
            int s   = tid + it * 256;
            int row = s >> 2;
            int kq  = (s & 3) * 4;
            float4 v = *(const float4*)&X[(m0 + row) * IND + k0 + kq];
            sA[kq + 0][row] = pack2(v.x, v.x);
            sA[kq + 1][row] = pack2(v.y, v.y);
            sA[kq + 2][row] = pack2(v.z, v.z);
            sA[kq + 3][row] = pack2(v.w, v.w);
        }
#pragma unroll
        for (int it = 0; it < 2; it++) {
            int s  = tid + it * 256;
            int kr = s >> 5;
            int nq = (s & 31) * 4;
            *(float4*)&sB[kr][nq] =
                *(const float4*)&W[(size_t)(k0 + kr) * UNITS + n0 + nq];
        }
        __syncthreads();

#pragma unroll
        for (int k = 0; k < BK; k++) {
            ull a[8];
#pragma unroll
            for (int i = 0; i < 8; i++) a[i] = sA[k][ty * 8 + i];
            const ull* b2 = (const ull*)&sB[k][tx * 8];
            ull b[4];
#pragma unroll
            for (int j = 0; j < 4; j++) b[j] = b2[j];
#pragma unroll
            for (int i = 0; i < 8; i++)
#pragma unroll
                for (int j = 0; j < 4; j++) fma2(acc[i][j], a[i], b[j]);
        }
        __syncthreads();
    }

    float bv[8];
#pragma unroll
    for (int j = 0; j < 8; j++) bv[j] = bias[n0 + tx * 8 + j];
#pragma unroll
    for (int i = 0; i < 8; i++) {
        size_t row = m0 + ty * 8 + i;
        float2 r0 = unpack2(acc[i][0]);
        float2 r1 = unpack2(acc[i][1]);
        float2 r2 = unpack2(acc[i][2]);
        float2 r3 = unpack2(acc[i][3]);
        float4 o0 = make_float4(r0.x + bv[0], r0.y + bv[1],
                                r1.x + bv[2], r1.y + bv[3]);
        float4 o1 = make_float4(r2.x + bv[4], r2.y + bv[5],
                                r3.x + bv[6], r3.y + bv[7]);
        *(float4*)&out[row * UNITS + n0 + tx * 8]     = o0;
        *(float4*)&out[row * UNITS + n0 + tx * 8 + 4] = o1;
    }
}

// ---------------------------------------------------------------------------
// Phase 2: cluster-2 scan, flag handshake (NO cluster barriers in the loop).
// 128 CTAs, 256 threads. Thread = (unit uL = t>>1, k-half kh = t&1);
// lane pair combines via shfl.bfly(1). Only 2 __syncthreads per step.
// Weights per thread per matrix: 64 pairs over its 128-wide k-half:
//   pairs 0..39  -> registers  (160 regs total; needs >128 => 256 thr/CTA max)
//   pairs 40..63 -> smem (96 KB total)
// h / fh vectors mirrored in both CTAs; 128-float slices exchanged via
// st.relaxed.cluster + one st.release.cluster flag per phase; consumers
// spin on a LOCAL flag with ld.acquire.cluster.
// ---------------------------------------------------------------------------
#define P_RF 40
#define SW_J 12
#define SW_BYTES (SW_J * 256 * 16)            // 49152 per matrix
#define VEC_BYTES 1088                        // 256 floats + 16B skew + pad
#define SH_OFF   (2 * SW_BYTES)               // 98304
#define SFH_OFF  (SH_OFF + VEC_BYTES)
#define FLG_OFF  (SFH_OFF + VEC_BYTES)
#define SMEM_SCAN (FLG_OFF + 64)              // 100544 bytes

__device__ __forceinline__ uint32_t ctarank() {
    uint32_t r;
    asm("mov.u32 %0, %%cluster_ctarank;" : "=r"(r));
    return r;
}
__device__ __forceinline__ uint32_t mapa_addr(const void* laddr, uint32_t peer) {
    uint32_t la = (uint32_t)__cvta_generic_to_shared(laddr);
    uint32_t ra;
    asm("mapa.shared::cluster.u32 %0, %1, %2;" : "=r"(ra) : "r"(la), "r"(peer));
    return ra;
}
__device__ __forceinline__ void st_rlx_remote(uint32_t ra, float v) {
    asm volatile("st.relaxed.cluster.shared::cluster.b32 [%0], %1;"
                 :: "r"(ra), "r"(__float_as_uint(v)) : "memory");
}
__device__ __forceinline__ void st_rel_remote(uint32_t ra, uint32_t v) {
    asm volatile("st.release.cluster.shared::cluster.b32 [%0], %1;"
                 :: "r"(ra), "r"(v) : "memory");
}
__device__ __forceinline__ uint32_t ld_acq_local(const uint32_t* p) {
    uint32_t la = (uint32_t)__cvta_generic_to_shared(p);
    uint32_t v;
    asm volatile("ld.acquire.cluster.shared::cta.b32 %0, [%1];"
                 : "=r"(v) : "r"(la) : "memory");
    return v;
}
__device__ __forceinline__ void spin_ge(const uint32_t* flag, uint32_t want) {
    while (ld_acq_local(flag) < want) {}
}

// Partial dot over a 128-wide k-half. vh: 32 x ulonglong2 (4 h floats each).
__device__ __forceinline__ float matvec_half(const ulonglong2* __restrict__ vh,
                                             const ull (&rW)[P_RF],
                                             const ulonglong2* __restrict__ sW,
                                             int t) {
    ull a0 = 0, a1 = 0, a2 = 0, a3 = 0;
#pragma unroll
    for (int j = 0; j < 20; j++) {              // pairs 0..39 (RF)
        ulonglong2 hv = vh[j];
        fma2(a0, hv.x, rW[2 * j]);
        fma2(a1, hv.y, rW[2 * j + 1]);
    }
#pragma unroll
    for (int j = 0; j < SW_J; j++) {            // pairs 40..63 (smem)
        ulonglong2 hv = vh[20 + j];
        ulonglong2 wv = sW[j * 256 + t];
        fma2(a2, hv.x, wv.x);
        fma2(a3, hv.y, wv.y);
    }
    add2(a0, a1);
    add2(a2, a3);
    add2(a0, a2);
    float2 r = unpack2(a0);
    return r.x + r.y;
}

__global__ __launch_bounds__(256, 1) __cluster_dims__(2, 1, 1)
void mgu_scan(const float* __restrict__ Uf, const float* __restrict__ Us,
              float* __restrict__ out) {
    extern __shared__ char smem[];
    ulonglong2* sWf = (ulonglong2*)smem;                 // [SW_J][256]
    ulonglong2* sWs = (ulonglong2*)(smem + SW_BYTES);
    float* shv  = (float*)(smem + SH_OFF);               // skewed h vector
    float* sfhv = (float*)(smem + SFH_OFF);              // skewed f*h vector
    uint32_t* flg = (uint32_t*)(smem + FLG_OFF);         // [0]=H, [8]=FH

    const int t  = threadIdx.x;
    const int uL = t >> 1;                // local unit 0..127
    const int kh = t & 1;                 // k-half
    const uint32_t rank = ctarank();
    const uint32_t peer = rank ^ 1u;
    const int ug = (int)rank * 128 + uL;  // global unit
    const int b  = blockIdx.x >> 1;       // batch row
    const int k0 = kh * 128;

    // ---- RF weight preload: pairs 0..39 -> k = k0 + [0,80) ----
    ull rF[P_RF], rS[P_RF];
#pragma unroll
    for (int p = 0; p < P_RF; p++) {
        rF[p] = pack2(Uf[(size_t)(k0 + 2 * p)     * UNITS + ug],
                      Uf[(size_t)(k0 + 2 * p + 1) * UNITS + ug]);
        rS[p] = pack2(Us[(size_t)(k0 + 2 * p)     * UNITS + ug],
                      Us[(size_t)(k0 + 2 * p + 1) * UNITS + ug]);
    }
    // ---- smem weight preload: slot j -> k = k0 + 80 + 4j ----
#pragma unroll
    for (int j = 0; j < SW_J; j++) {
        int kk = k0 + 80 + 4 * j;
        sWf[j * 256 + t] = make_ulonglong2(
            pack2(Uf[(size_t)kk       * UNITS + ug], Uf[(size_t)(kk + 1) * UNITS + ug]),
            pack2(Uf[(size_t)(kk + 2) * UNITS + ug], Uf[(size_t)(kk + 3) * UNITS + ug]));
        sWs[j * 256 + t] = make_ulonglong2(
            pack2(Us[(size_t)kk       * UNITS + ug], Us[(size_t)(kk + 1) * UNITS + ug]),
            pack2(Us[(size_t)(kk + 2) * UNITS + ug], Us[(size_t)(kk + 3) * UNITS + ug]));
    }
    // init vectors (incl. skew pad) + flags
    if (t < 136) { shv[t] = 0.0f; sfhv[t] = 0.0f;
                   shv[136 + t] = 0.0f; sfhv[136 + t] = 0.0f; }
    if (t == 0) { flg[0] = 0u; flg[8] = 0u; }
    __syncthreads();
    asm volatile("barrier.cluster.arrive.aligned;" ::: "memory");
    asm volatile("barrier.cluster.wait.aligned;"   ::: "memory");

    // Skewed float offset for unit ug: +4 floats if upper half.
    const int voff = ug + ((int)rank) * 4;            // ug>=128 iff rank==1
    const ulonglong2* vh_h  = (const ulonglong2*)((char*)shv  + kh * 528);
    const ulonglong2* vh_fh = (const ulonglong2*)((char*)sfhv + kh * 528);

    // Remote addresses (owner lanes kh==0 store data; t0 stores flags)
    uint32_t ra_fh = 0, ra_h = 0, ra_flag_fh = 0, ra_flag_h = 0;
    if (kh == 0) {
        ra_fh = mapa_addr(&sfhv[voff], peer);
        ra_h  = mapa_addr(&shv[voff],  peer);
    }
    if (t == 0) {
        ra_flag_h  = mapa_addr(&flg[0], peer);
        ra_flag_fh = mapa_addr(&flg[8], peer);
    }

    const bool remote_half = (kh != (int)rank);   // this k-half reads peer data
    float h_reg = 0.0f;
    size_t xoff = ((size_t)b * SEQ) * UNITS + ug;

    for (int step = 0; step < SEQ; step++) {
        float xf_v = __ldcg(&g_xf[xoff]);
        float xs_v = __ldcg(&g_xs[xoff]);

        // ---- matvec 1: h @ U_f ----
        if (remote_half) spin_ge(&flg[0], (uint32_t)step);
        float p1 = matvec_half(vh_h, rF, sWf, t);
        p1 += __shfl_xor_sync(0xffffffffu, p1, 1);
        float fpre = xf_v + p1;
        float f = 1.0f / (1.0f + __expf(-fpre));
        float fh = f * h_reg;
        if (kh == 0) { sfhv[voff] = fh; st_rlx_remote(ra_fh, fh); }
        __syncthreads();                                   // S_a
        if (t == 0) st_rel_remote(ra_flag_fh, (uint32_t)(step + 1));

        // ---- matvec 2: (f*h) @ U_s ----
        if (remote_half) spin_ge(&flg[8], (uint32_t)(step + 1));
        float p2 = matvec_half(vh_fh, rS, sWs, t);
        p2 += __shfl_xor_sync(0xffffffffu, p2, 1);
        float spre = xs_v + p2;
        float ax = fabsf(spre);
        float e  = __expf(-2.0f * ax);
        float th = (1.0f - e) / (1.0f + e);                // overflow-safe tanh
        th = copysignf(th, spre);

        float hn = h_reg + f * (th - h_reg);               // (1-f)h + f*th
        if (kh == 0) {
            out[xoff] = hn;
            shv[voff] = hn;
            st_rlx_remote(ra_h, hn);
        }
        h_reg = hn;
        xoff += UNITS;
        __syncthreads();                                   // S_b
        if (t == 0) st_rel_remote(ra_flag_h, (uint32_t)(step + 1));
    }

    // Don't exit while the peer may still write into our smem.
    asm volatile("barrier.cluster.arrive.aligned;" ::: "memory");
    asm volatile("barrier.cluster.wait.aligned;"   ::: "memory");
}

// ---------------------------------------------------------------------------
// Entry point
// ---------------------------------------------------------------------------
extern "C" void kernel_launch(void* const* d_in, const int* in_sizes, int n_in,
                              void* d_out, int out_size) {
    const float* X  = (const float*)d_in[0];
    const float* Wf = (const float*)d_in[1];
    const float* Uf = (const float*)d_in[2];
    const float* bf = (const float*)d_in[3];
    const float* Ws = (const float*)d_in[4];
    const float* Us = (const float*)d_in[5];
    const float* bs = (const float*)d_in[6];
    float* out = (float*)d_out;
    (void)in_sizes; (void)n_in; (void)out_size;

    cudaFuncSetAttribute(mgu_scan,
                         cudaFuncAttributeMaxDynamicSharedMemorySize, SMEM_SCAN);

    gemm_in<<<dim3(M_TOTAL / BM, 4), 256>>>(X, Wf, bf, Ws, bs);
    mgu_scan<<<2 * BATCH, 256, SMEM_SCAN>>>(Uf, Us, out);
}